// round 1
// baseline (speedup 1.0000x reference)
#include <cuda_runtime.h>

#define NB 32
#define NP 8732
#define NC 81
#define WPB 8
#define GX ((NP + WPB - 1) / WPB)   // 1092
#define NBLK (NB * GX)

// Scratch (device globals — no allocation). Fully rewritten every replay.
__device__ float g_ce[NB * NP];
__device__ float g_key[NB * NP];
__device__ float g_part_ce[NBLK];
__device__ float g_part_sl1[NBLK];
__device__ int   g_part_pos[NBLK];
__device__ int   g_num_pos[NB];
__device__ float g_cls_b[NB];
__device__ float g_sl1_b[NB];
__device__ float g_cls_neg[NB];

__device__ __forceinline__ unsigned flipf(float f) {
    unsigned u = __float_as_uint(f);
    return u ^ ((u >> 31) ? 0xffffffffu : 0x80000000u);
}

// Kernel 1: per-prior LSE / CE / mining key / smooth-L1, per-block partials.
__global__ void k_main(const float* __restrict__ conf,
                       const float* __restrict__ pred,
                       const int*   __restrict__ labels,
                       const float* __restrict__ gt) {
    const float NEG_INF = __int_as_float((int)0xff800000u);
    int b    = blockIdx.y;
    int warp = threadIdx.x >> 5;
    int lane = threadIdx.x & 31;
    int p    = blockIdx.x * WPB + warp;

    __shared__ float s_ce[WPB], s_sl1[WPB];
    __shared__ int   s_pos[WPB];

    float warp_ce = 0.f, warp_sl1 = 0.f;
    int pos = 0;

    if (p < NP) {
        long long i = (long long)b * NP + p;
        const float* row = conf + i * NC;
        float v0 = row[lane];
        float v1 = row[lane + 32];
        float v2 = (lane < NC - 64) ? row[lane + 64] : NEG_INF;

        float m = fmaxf(fmaxf(v0, v1), v2);
        #pragma unroll
        for (int o = 16; o; o >>= 1) m = fmaxf(m, __shfl_xor_sync(0xffffffffu, m, o));

        float e = expf(v0 - m) + expf(v1 - m) + ((lane < NC - 64) ? expf(v2 - m) : 0.f);
        int lab = labels[i];
        float t = (lane == lab ? v0 : 0.f)
                + (lane + 32 == lab ? v1 : 0.f)
                + ((lane < NC - 64 && lane + 64 == lab) ? v2 : 0.f);
        #pragma unroll
        for (int o = 16; o; o >>= 1) {
            e += __shfl_xor_sync(0xffffffffu, e, o);
            t += __shfl_xor_sync(0xffffffffu, t, o);
        }
        float lse   = m + logf(e);
        float conf0 = __shfl_sync(0xffffffffu, v0, 0);

        float ce  = lse - t;             // per-prior cross entropy
        pos       = lab > 0;
        float key = pos ? NEG_INF : (lse - conf0);   // background loss for mining

        if (lane == 0) { g_ce[i] = ce; g_key[i] = key; }

        warp_ce = pos ? ce : 0.f;

        float sl1 = 0.f;
        if (pos && lane < 4) {
            float d  = pred[i * 4 + lane] - gt[i * 4 + lane];
            float ad = fabsf(d);
            sl1 = (ad < 1.f) ? 0.5f * d * d : (ad - 0.5f);
        }
        #pragma unroll
        for (int o = 16; o; o >>= 1) sl1 += __shfl_xor_sync(0xffffffffu, sl1, o);
        warp_sl1 = sl1;
    }

    if (lane == 0) { s_ce[warp] = warp_ce; s_sl1[warp] = warp_sl1; s_pos[warp] = pos; }
    __syncthreads();
    if (threadIdx.x == 0) {
        float ce = 0.f, sl = 0.f; int np = 0;
        #pragma unroll
        for (int w = 0; w < WPB; w++) { ce += s_ce[w]; sl += s_sl1[w]; np += s_pos[w]; }
        int bid = b * GX + blockIdx.x;
        g_part_ce[bid]  = ce;
        g_part_sl1[bid] = sl;
        g_part_pos[bid] = np;
    }
}

// Kernel 2: per-batch reduction of block partials.
__global__ void k_batch_reduce() {
    int b = blockIdx.x, tid = threadIdx.x;
    float ce = 0.f, sl = 0.f; int np = 0;
    for (int j = tid; j < GX; j += blockDim.x) {
        int bid = b * GX + j;
        ce += g_part_ce[bid]; sl += g_part_sl1[bid]; np += g_part_pos[bid];
    }
    #pragma unroll
    for (int o = 16; o; o >>= 1) {
        ce += __shfl_xor_sync(0xffffffffu, ce, o);
        sl += __shfl_xor_sync(0xffffffffu, sl, o);
        np += __shfl_xor_sync(0xffffffffu, np, o);
    }
    __shared__ float sc[8], ss[8];
    __shared__ int   sp[8];
    int w = tid >> 5, l = tid & 31;
    if (l == 0) { sc[w] = ce; ss[w] = sl; sp[w] = np; }
    __syncthreads();
    if (tid == 0) {
        float c = 0.f, s = 0.f; int n = 0;
        #pragma unroll
        for (int i = 0; i < 8; i++) { c += sc[i]; s += ss[i]; n += sp[i]; }
        g_cls_b[b]   = c;
        g_sl1_b[b]   = s;
        g_num_pos[b] = n;
    }
}

// Kernel 3: per-batch hard-negative selection (top-k by bg loss, stable-index ties).
__global__ void k_select() {
    const int BS = 1024;
    int b = blockIdx.x, tid = threadIdx.x;
    long long base = (long long)b * NP;
    int k = 3 * g_num_pos[b];

    // Count negatives + total negative CE (fast path: take all)
    int cnt = 0; float sneg = 0.f;
    for (int p = tid; p < NP; p += BS) {
        unsigned kb = __float_as_uint(g_key[base + p]);
        if (kb != 0xff800000u) { cnt++; sneg += g_ce[base + p]; }
    }
    #pragma unroll
    for (int o = 16; o; o >>= 1) {
        cnt  += __shfl_xor_sync(0xffffffffu, cnt, o);
        sneg += __shfl_xor_sync(0xffffffffu, sneg, o);
    }
    __shared__ int   sc_i[32];
    __shared__ float sc_f[32];
    int w = tid >> 5, l = tid & 31;
    if (l == 0) { sc_i[w] = cnt; sc_f[w] = sneg; }
    __syncthreads();
    __shared__ int s_nneg; __shared__ float s_sneg;
    if (tid == 0) {
        int c = 0; float s = 0.f;
        #pragma unroll
        for (int i = 0; i < 32; i++) { c += sc_i[i]; s += sc_f[i]; }
        s_nneg = c; s_sneg = s;
    }
    __syncthreads();
    int nNeg = s_nneg;

    if (k >= nNeg) {                       // all negatives selected
        if (tid == 0) g_cls_neg[b] = s_sneg;
        return;
    }
    if (k <= 0) {
        if (tid == 0) g_cls_neg[b] = 0.f;
        return;
    }

    // Radix-select the k-th largest flipped-float key (4 passes of 8 bits).
    __shared__ unsigned hist[256];
    __shared__ unsigned s_chosen;
    __shared__ int      s_kk;
    unsigned prefix = 0, prefmask = 0;
    int kk = k;
    for (int shift = 24; shift >= 0; shift -= 8) {
        if (tid < 256) hist[tid] = 0;
        __syncthreads();
        for (int p = tid; p < NP; p += BS) {
            unsigned u = flipf(g_key[base + p]);
            if ((u & prefmask) == prefix) atomicAdd(&hist[(u >> shift) & 255], 1u);
        }
        __syncthreads();
        if (tid == 0) {
            int cum = 0; int chosen = 0;
            for (int bin = 255; bin >= 0; bin--) {
                int h = (int)hist[bin];
                if (cum + h >= kk) { chosen = bin; break; }
                cum += h;
            }
            s_chosen = (unsigned)chosen;
            s_kk     = kk - cum;
        }
        __syncthreads();
        prefix  |= s_chosen << shift;
        prefmask |= 255u << shift;
        kk = s_kk;
        __syncthreads();
    }
    unsigned T = prefix;   // bits of the k-th largest key

    float ssel = 0.f;
    for (int p = tid; p < NP; p += BS) {
        unsigned u = flipf(g_key[base + p]);
        if (u > T) ssel += g_ce[base + p];
    }
    #pragma unroll
    for (int o = 16; o; o >>= 1) ssel += __shfl_xor_sync(0xffffffffu, ssel, o);
    if (l == 0) sc_f[w] = ssel;
    __syncthreads();
    if (tid == 0) {
        float tot = 0.f;
        #pragma unroll
        for (int i = 0; i < 32; i++) tot += sc_f[i];
        // Ties at threshold: stable order = ascending index (matches JAX stable argsort)
        int r = kk;
        for (int p = 0; p < NP && r > 0; p++) {
            if (flipf(g_key[base + p]) == T) { tot += g_ce[base + p]; r--; }
        }
        g_cls_neg[b] = tot;
    }
}

// Kernel 4: finalize.
__global__ void k_final(float* __restrict__ out, int out_size) {
    if (threadIdx.x == 0) {
        int np = 0; float cls = 0.f, sl = 0.f;
        #pragma unroll
        for (int b = 0; b < NB; b++) {
            np  += g_num_pos[b];
            cls += g_cls_b[b] + g_cls_neg[b];
            sl  += g_sl1_b[b];
        }
        float fn = (float)np;
        out[0] = sl / fn;
        if (out_size > 1) out[1] = cls / fn;
    }
}

extern "C" void kernel_launch(void* const* d_in, const int* in_sizes, int n_in,
                              void* d_out, int out_size) {
    const float* conf   = (const float*)d_in[0];
    const float* pred   = (const float*)d_in[1];
    const int*   labels = (const int*)d_in[2];
    const float* gt     = (const float*)d_in[3];
    float* out = (float*)d_out;

    dim3 g1(GX, NB);
    k_main<<<g1, WPB * 32>>>(conf, pred, labels, gt);
    k_batch_reduce<<<NB, 256>>>();
    k_select<<<NB, 1024>>>();
    k_final<<<1, 32>>>(out, out_size);
}